// round 7
// baseline (speedup 1.0000x reference)
#include <cuda_runtime.h>
#include <cuda_bf16.h>

// Problem constants (match reference)
#define N_NODES 50000
#define N_EDGES 800000
#define N_FEAT  128
#define DIM     64
#define N_GRAPHS 512
#define SCAN_BLOCKS ((N_NODES + 255) / 256)   // 196

// Scratch (device globals — no allocation allowed)
__device__ __align__(16) float g_h[N_NODES * DIM];      // gemm1 output
__device__ __align__(16) float g_agg1[N_NODES * DIM];   // relu(A @ h1)
__device__ __align__(16) float g_pooled[N_GRAPHS * DIM];
// CSR (by destination)
__device__ __align__(16) int g_deg[N_NODES];
__device__ int g_off[N_NODES + 1];
__device__ int g_cursor[N_NODES];
__device__ int g_csr[N_EDGES];
__device__ int g_bsum[SCAN_BLOCKS];

// ---------------------------------------------------------------------------
// Zero small state
// ---------------------------------------------------------------------------
__global__ void zero_kernel() {
    int i = blockIdx.x * blockDim.x + threadIdx.x;
    if (i < N_NODES) g_deg[i] = 0;
    if (i < N_GRAPHS * (DIM / 4))
        ((float4*)g_pooled)[i] = make_float4(0.f, 0.f, 0.f, 0.f);
    if (i == 0) g_off[N_NODES] = N_EDGES;   // known total
}

// ---------------------------------------------------------------------------
// CSR build: int4 histogram, 2-kernel scan, int4 atomic-bump fill
// ---------------------------------------------------------------------------
__global__ void hist_kernel(const int* __restrict__ ei) {
    int t = blockIdx.x * blockDim.x + threadIdx.x;
    if (t >= N_EDGES / 4) return;
    int4 d = ((const int4*)(ei + N_EDGES))[t];
    atomicAdd(&g_deg[d.x], 1);
    atomicAdd(&g_deg[d.y], 1);
    atomicAdd(&g_deg[d.z], 1);
    atomicAdd(&g_deg[d.w], 1);
}

// block sums of deg
__global__ void scan_sums_kernel() {
    __shared__ int sd[256];
    int tid = threadIdx.x;
    int i = blockIdx.x * 256 + tid;
    sd[tid] = (i < N_NODES) ? g_deg[i] : 0;
    __syncthreads();
    for (int s = 128; s > 0; s >>= 1) {
        if (tid < s) sd[tid] += sd[tid + s];
        __syncthreads();
    }
    if (tid == 0) g_bsum[blockIdx.x] = sd[0];
}

// per-block: base = sum of previous block sums (reduction), then
// shuffle exclusive scan within block -> g_off, g_cursor
__global__ void scan_final_kernel() {
    __shared__ int red[256];
    __shared__ int wsum[8];
    __shared__ int blockBase;
    int tid = threadIdx.x;
    int bid = blockIdx.x;

    // block base: sum of g_bsum[0..bid)
    int part = 0;
    for (int t = tid; t < bid; t += 256) part += g_bsum[t];
    red[tid] = part;
    __syncthreads();
    for (int s = 128; s > 0; s >>= 1) {
        if (tid < s) red[tid] += red[tid + s];
        __syncthreads();
    }
    if (tid == 0) blockBase = red[0];

    int i = bid * 256 + tid;
    int v = (i < N_NODES) ? g_deg[i] : 0;
    int lane = tid & 31, wid = tid >> 5;
    int inc = v;
    #pragma unroll
    for (int off = 1; off < 32; off <<= 1) {
        int u = __shfl_up_sync(0xffffffff, inc, off);
        if (lane >= off) inc += u;
    }
    if (lane == 31) wsum[wid] = inc;
    __syncthreads();
    if (wid == 0) {
        int w = (lane < 8) ? wsum[lane] : 0;
        #pragma unroll
        for (int off = 1; off < 8; off <<= 1) {
            int u = __shfl_up_sync(0xffffffff, w, off);
            if (lane >= off) w += u;
        }
        if (lane < 8) wsum[lane] = w;
    }
    __syncthreads();
    int warpBase = (wid == 0) ? 0 : wsum[wid - 1];
    int excl = blockBase + warpBase + inc - v;
    if (i < N_NODES) {
        g_off[i] = excl;
        g_cursor[i] = excl;
    }
}

__global__ void fill_kernel(const int* __restrict__ ei) {
    int t = blockIdx.x * blockDim.x + threadIdx.x;
    if (t >= N_EDGES / 4) return;
    int4 s = ((const int4*)ei)[t];
    int4 d = ((const int4*)(ei + N_EDGES))[t];
    int p0 = atomicAdd(&g_cursor[d.x], 1);
    int p1 = atomicAdd(&g_cursor[d.y], 1);
    int p2 = atomicAdd(&g_cursor[d.z], 1);
    int p3 = atomicAdd(&g_cursor[d.w], 1);
    g_csr[p0] = s.x; g_csr[p1] = s.y; g_csr[p2] = s.z; g_csr[p3] = s.w;
}

// ---------------------------------------------------------------------------
// GEMM1: g_h[N,64] = x[N,128] @ W1[128,64], packed fma.rn.f32x2.
// Block = 256 threads / 128 rows; thread: 4 rows x 8 cols.
// ---------------------------------------------------------------------------
typedef unsigned long long u64;

__global__ void gemm1_kernel(const float4* __restrict__ xin,
                             const float* __restrict__ W) {
    constexpr int K = N_FEAT;
    constexpr int NC4 = K / 4;
    constexpr int CHUNK = 16;
    constexpr int NCHUNK = K / CHUNK;
    __shared__ __align__(16) float Ws[K * 64];
    __shared__ __align__(16) float xs[128 * 20];

    int tid = threadIdx.x;
    for (int i = tid; i < K * 16; i += 256)
        ((float4*)Ws)[i] = ((const float4*)W)[i];

    int rowBase = blockIdx.x * 128;
    int q  = tid >> 3;
    int cg = tid & 7;

    u64 acc[4][4];
    #pragma unroll
    for (int i = 0; i < 4; i++)
        #pragma unroll
        for (int j = 0; j < 4; j++) acc[i][j] = 0ULL;

    for (int ch = 0; ch < NCHUNK; ch++) {
        __syncthreads();
        for (int l = tid; l < 512; l += 256) {
            int r = l >> 2, j = l & 3;
            int gr = rowBase + r;
            float4 v = make_float4(0.f, 0.f, 0.f, 0.f);
            if (gr < N_NODES) v = xin[gr * NC4 + ch * 4 + j];
            *(float4*)&xs[r * 20 + j * 4] = v;
        }
        __syncthreads();

        #pragma unroll
        for (int k4 = 0; k4 < CHUNK / 4; k4++) {
            float4 xv[4];
            #pragma unroll
            for (int i = 0; i < 4; i++)
                xv[i] = *(const float4*)&xs[(q + 32 * i) * 20 + k4 * 4];
            #pragma unroll
            for (int kk = 0; kk < 4; kk++) {
                int k = ch * CHUNK + k4 * 4 + kk;
                const double2* Wp = (const double2*)&Ws[k * 64 + cg * 8];
                double2 wA = Wp[0], wB = Wp[1];
                u64 w0 = __double_as_longlong(wA.x);
                u64 w1 = __double_as_longlong(wA.y);
                u64 w2 = __double_as_longlong(wB.x);
                u64 w3 = __double_as_longlong(wB.y);
                #pragma unroll
                for (int i = 0; i < 4; i++) {
                    float xf = (kk == 0) ? xv[i].x : (kk == 1) ? xv[i].y
                             : (kk == 2) ? xv[i].z : xv[i].w;
                    u64 xp;
                    asm("mov.b64 %0, {%1, %2};" : "=l"(xp) : "f"(xf), "f"(xf));
                    asm("fma.rn.f32x2 %0, %1, %2, %0;" : "+l"(acc[i][0]) : "l"(xp), "l"(w0));
                    asm("fma.rn.f32x2 %0, %1, %2, %0;" : "+l"(acc[i][1]) : "l"(xp), "l"(w1));
                    asm("fma.rn.f32x2 %0, %1, %2, %0;" : "+l"(acc[i][2]) : "l"(xp), "l"(w2));
                    asm("fma.rn.f32x2 %0, %1, %2, %0;" : "+l"(acc[i][3]) : "l"(xp), "l"(w3));
                }
            }
        }
    }

    #pragma unroll
    for (int i = 0; i < 4; i++) {
        int r = rowBase + q + 32 * i;
        if (r < N_NODES) {
            float4 o0, o1;
            asm("mov.b64 {%0, %1}, %2;" : "=f"(o0.x), "=f"(o0.y) : "l"(acc[i][0]));
            asm("mov.b64 {%0, %1}, %2;" : "=f"(o0.z), "=f"(o0.w) : "l"(acc[i][1]));
            asm("mov.b64 {%0, %1}, %2;" : "=f"(o1.x), "=f"(o1.y) : "l"(acc[i][2]));
            asm("mov.b64 {%0, %1}, %2;" : "=f"(o1.z), "=f"(o1.w) : "l"(acc[i][3]));
            ((float4*)g_h)[r * 16 + cg * 2]     = o0;
            ((float4*)g_h)[r * 16 + cg * 2 + 1] = o1;
        }
    }
}

// ---------------------------------------------------------------------------
// Gather 1: agg1[n] = relu( sum_{s in CSR[n]} h[s] ). 16 lanes/node, 4-way MLP.
// ---------------------------------------------------------------------------
__global__ void gather1_kernel() {
    const float4* h = (const float4*)g_h;
    float4* agg = (float4*)g_agg1;
    int t = blockIdx.x * blockDim.x + threadIdx.x;
    if (t >= N_NODES * 16) return;
    int n = t >> 4, c = t & 15;
    int b = g_off[n], e = g_off[n + 1];
    float4 acc = make_float4(0.f, 0.f, 0.f, 0.f);
    int i = b;
    for (; i + 3 < e; i += 4) {
        int s0 = g_csr[i], s1 = g_csr[i+1], s2 = g_csr[i+2], s3 = g_csr[i+3];
        float4 v0 = h[s0 * 16 + c];
        float4 v1 = h[s1 * 16 + c];
        float4 v2 = h[s2 * 16 + c];
        float4 v3 = h[s3 * 16 + c];
        acc.x += v0.x + v1.x + v2.x + v3.x;
        acc.y += v0.y + v1.y + v2.y + v3.y;
        acc.z += v0.z + v1.z + v2.z + v3.z;
        acc.w += v0.w + v1.w + v2.w + v3.w;
    }
    for (; i < e; i++) {
        int s = g_csr[i];
        float4 v = h[s * 16 + c];
        acc.x += v.x; acc.y += v.y; acc.z += v.z; acc.w += v.w;
    }
    acc.x = fmaxf(acc.x, 0.f); acc.y = fmaxf(acc.y, 0.f);
    acc.z = fmaxf(acc.z, 0.f); acc.w = fmaxf(acc.w, 0.f);
    agg[n * 16 + c] = acc;
}

// ---------------------------------------------------------------------------
// Gather 2 fused with pooling. batch is SORTED: the 16 nodes of a block almost
// always share one graph id -> aggregate in smem, one RED per column for the
// common graph; direct RED only for boundary nodes.
// ---------------------------------------------------------------------------
__global__ void gather2_pool_kernel(const int* __restrict__ batch) {
    __shared__ __align__(16) float4 sacc[256];   // [node 0..15][col 0..15]
    const float4* h = (const float4*)g_agg1;
    float4* pooled = (float4*)g_pooled;

    int tid = threadIdx.x;
    int nb = blockIdx.x * 16;
    int ln = tid >> 4, c = tid & 15;
    int n = nb + ln;

    int b = g_off[n], e = g_off[n + 1];
    float4 acc = make_float4(0.f, 0.f, 0.f, 0.f);
    int i = b;
    for (; i + 3 < e; i += 4) {
        int s0 = g_csr[i], s1 = g_csr[i+1], s2 = g_csr[i+2], s3 = g_csr[i+3];
        float4 v0 = h[s0 * 16 + c];
        float4 v1 = h[s1 * 16 + c];
        float4 v2 = h[s2 * 16 + c];
        float4 v3 = h[s3 * 16 + c];
        acc.x += v0.x + v1.x + v2.x + v3.x;
        acc.y += v0.y + v1.y + v2.y + v3.y;
        acc.z += v0.z + v1.z + v2.z + v3.z;
        acc.w += v0.w + v1.w + v2.w + v3.w;
    }
    for (; i < e; i++) {
        int s = g_csr[i];
        float4 v = h[s * 16 + c];
        acc.x += v.x; acc.y += v.y; acc.z += v.z; acc.w += v.w;
    }

    int g  = batch[n];
    int g0 = batch[nb];
    bool common = (g == g0);
    sacc[ln * 16 + c] = common ? acc : make_float4(0.f, 0.f, 0.f, 0.f);
    if (!common) atomicAdd(&pooled[g * 16 + c], acc);
    __syncthreads();
    #pragma unroll
    for (int s = 8; s > 0; s >>= 1) {
        if (ln < s) {
            float4 a = sacc[ln * 16 + c], bb = sacc[(ln + s) * 16 + c];
            a.x += bb.x; a.y += bb.y; a.z += bb.z; a.w += bb.w;
            sacc[ln * 16 + c] = a;
        }
        __syncthreads();
    }
    if (ln == 0) atomicAdd(&pooled[g0 * 16 + c], sacc[c]);
}

// ---------------------------------------------------------------------------
// Final: wv = W2 @ Wfc; counts via binary search on sorted batch;
// out[g] = sigmoid( dot(pooled[g], wv) / max(cnt,1) )
// ---------------------------------------------------------------------------
__global__ void final_kernel(const int* __restrict__ batch,
                             const float* __restrict__ W2,
                             const float* __restrict__ Wfc,
                             float* __restrict__ out) {
    __shared__ float wv[DIM];
    int tid = threadIdx.x;
    if (tid < DIM) {
        float s = 0.f;
        #pragma unroll
        for (int d = 0; d < DIM; d++)
            s += W2[tid * DIM + d] * Wfc[d];
        wv[tid] = s;
    }
    __syncthreads();
    if (tid >= N_GRAPHS) return;

    // count of nodes with batch == tid (batch sorted): lb(tid+1) - lb(tid)
    int lo = 0, hi = N_NODES;
    while (lo < hi) { int m = (lo + hi) >> 1; if (batch[m] < tid) lo = m + 1; else hi = m; }
    int b0 = lo;
    lo = 0; hi = N_NODES;
    while (lo < hi) { int m = (lo + hi) >> 1; if (batch[m] < tid + 1) lo = m + 1; else hi = m; }
    float cnt = fmaxf((float)(lo - b0), 1.0f);

    float s = 0.f;
    #pragma unroll
    for (int d = 0; d < DIM; d++)
        s += g_pooled[tid * DIM + d] * wv[d];
    s /= cnt;
    out[tid] = 1.0f / (1.0f + expf(-s));
}

// ---------------------------------------------------------------------------
extern "C" void kernel_launch(void* const* d_in, const int* in_sizes, int n_in,
                              void* d_out, int out_size) {
    const float* x    = (const float*)d_in[0];
    const int*   ei   = (const int*)d_in[1];
    const int*   batch= (const int*)d_in[2];
    const float* W1   = (const float*)d_in[3];
    const float* W2   = (const float*)d_in[4];
    const float* Wfc  = (const float*)d_in[5];
    float*       out  = (float*)d_out;

    zero_kernel<<<(N_NODES + 255) / 256, 256>>>();
    hist_kernel<<<(N_EDGES / 4 + 255) / 256, 256>>>(ei);
    scan_sums_kernel<<<SCAN_BLOCKS, 256>>>();
    scan_final_kernel<<<SCAN_BLOCKS, 256>>>();
    fill_kernel<<<(N_EDGES / 4 + 255) / 256, 256>>>(ei);

    gemm1_kernel<<<(N_NODES + 127) / 128, 256>>>((const float4*)x, W1);
    gather1_kernel<<<(N_NODES * 16) / 256, 256>>>();
    gather2_pool_kernel<<<N_NODES / 16, 256>>>(batch);

    final_kernel<<<1, N_GRAPHS>>>(batch, W2, Wfc, out);
}

// round 8
// speedup vs baseline: 1.4753x; 1.4753x over previous
#include <cuda_runtime.h>
#include <cuda_bf16.h>

// Problem constants (match reference)
#define N_NODES 50000
#define N_EDGES 800000
#define N_FEAT  128
#define DIM     64
#define N_GRAPHS 512
#define SCAN_BLOCKS ((N_NODES + 255) / 256)   // 196

// Scratch (device globals — no allocation allowed)
__device__ __align__(16) float g_h[N_NODES * DIM];      // gemm1 output
__device__ __align__(16) float g_agg1[N_NODES * DIM];   // relu(A @ h1)
__device__ __align__(16) float g_pooled[N_GRAPHS * DIM];
// CSR (by destination)
__device__ __align__(16) int g_deg[N_NODES];
__device__ int g_off[N_NODES + 1];
__device__ int g_cursor[N_NODES];
__device__ int g_csr[N_EDGES];
__device__ int g_bsum[SCAN_BLOCKS];

// ---------------------------------------------------------------------------
// Zero small state
// ---------------------------------------------------------------------------
__global__ void zero_kernel() {
    int i = blockIdx.x * blockDim.x + threadIdx.x;
    if (i < N_NODES) g_deg[i] = 0;
    if (i < N_GRAPHS * (DIM / 4))
        ((float4*)g_pooled)[i] = make_float4(0.f, 0.f, 0.f, 0.f);
    if (i == 0) g_off[N_NODES] = N_EDGES;   // known total
}

// ---------------------------------------------------------------------------
// CSR build: int4 histogram, 2-kernel scan, int4 atomic-bump fill
// ---------------------------------------------------------------------------
__global__ void hist_kernel(const int* __restrict__ ei) {
    int t = blockIdx.x * blockDim.x + threadIdx.x;
    if (t >= N_EDGES / 4) return;
    int4 d = ((const int4*)(ei + N_EDGES))[t];
    atomicAdd(&g_deg[d.x], 1);
    atomicAdd(&g_deg[d.y], 1);
    atomicAdd(&g_deg[d.z], 1);
    atomicAdd(&g_deg[d.w], 1);
}

// block sums of deg
__global__ void scan_sums_kernel() {
    __shared__ int sd[256];
    int tid = threadIdx.x;
    int i = blockIdx.x * 256 + tid;
    sd[tid] = (i < N_NODES) ? g_deg[i] : 0;
    __syncthreads();
    for (int s = 128; s > 0; s >>= 1) {
        if (tid < s) sd[tid] += sd[tid + s];
        __syncthreads();
    }
    if (tid == 0) g_bsum[blockIdx.x] = sd[0];
}

// per-block: base = sum of previous block sums (reduction), then
// shuffle exclusive scan within block -> g_off, g_cursor
__global__ void scan_final_kernel() {
    __shared__ int red[256];
    __shared__ int wsum[8];
    __shared__ int blockBase;
    int tid = threadIdx.x;
    int bid = blockIdx.x;

    // block base: sum of g_bsum[0..bid)
    int part = 0;
    for (int t = tid; t < bid; t += 256) part += g_bsum[t];
    red[tid] = part;
    __syncthreads();
    for (int s = 128; s > 0; s >>= 1) {
        if (tid < s) red[tid] += red[tid + s];
        __syncthreads();
    }
    if (tid == 0) blockBase = red[0];

    int i = bid * 256 + tid;
    int v = (i < N_NODES) ? g_deg[i] : 0;
    int lane = tid & 31, wid = tid >> 5;
    int inc = v;
    #pragma unroll
    for (int off = 1; off < 32; off <<= 1) {
        int u = __shfl_up_sync(0xffffffff, inc, off);
        if (lane >= off) inc += u;
    }
    if (lane == 31) wsum[wid] = inc;
    __syncthreads();
    if (wid == 0) {
        int w = (lane < 8) ? wsum[lane] : 0;
        #pragma unroll
        for (int off = 1; off < 8; off <<= 1) {
            int u = __shfl_up_sync(0xffffffff, w, off);
            if (lane >= off) w += u;
        }
        if (lane < 8) wsum[lane] = w;
    }
    __syncthreads();
    int warpBase = (wid == 0) ? 0 : wsum[wid - 1];
    int excl = blockBase + warpBase + inc - v;
    if (i < N_NODES) {
        g_off[i] = excl;
        g_cursor[i] = excl;
    }
}

__global__ void fill_kernel(const int* __restrict__ ei) {
    int t = blockIdx.x * blockDim.x + threadIdx.x;
    if (t >= N_EDGES / 4) return;
    int4 s = ((const int4*)ei)[t];
    int4 d = ((const int4*)(ei + N_EDGES))[t];
    int p0 = atomicAdd(&g_cursor[d.x], 1);
    int p1 = atomicAdd(&g_cursor[d.y], 1);
    int p2 = atomicAdd(&g_cursor[d.z], 1);
    int p3 = atomicAdd(&g_cursor[d.w], 1);
    g_csr[p0] = s.x; g_csr[p1] = s.y; g_csr[p2] = s.z; g_csr[p3] = s.w;
}

// ---------------------------------------------------------------------------
// GEMM1: g_h[N,64] = x[N,128] @ W1[128,64], packed fma.rn.f32x2.
// Block = 256 threads / 128 rows; thread: 4 rows x 8 cols.
// ---------------------------------------------------------------------------
typedef unsigned long long u64;

__global__ void gemm1_kernel(const float4* __restrict__ xin,
                             const float* __restrict__ W) {
    constexpr int K = N_FEAT;
    constexpr int NC4 = K / 4;
    constexpr int CHUNK = 16;
    constexpr int NCHUNK = K / CHUNK;
    __shared__ __align__(16) float Ws[K * 64];
    __shared__ __align__(16) float xs[128 * 20];

    int tid = threadIdx.x;
    for (int i = tid; i < K * 16; i += 256)
        ((float4*)Ws)[i] = ((const float4*)W)[i];

    int rowBase = blockIdx.x * 128;
    int q  = tid >> 3;
    int cg = tid & 7;

    u64 acc[4][4];
    #pragma unroll
    for (int i = 0; i < 4; i++)
        #pragma unroll
        for (int j = 0; j < 4; j++) acc[i][j] = 0ULL;

    for (int ch = 0; ch < NCHUNK; ch++) {
        __syncthreads();
        for (int l = tid; l < 512; l += 256) {
            int r = l >> 2, j = l & 3;
            int gr = rowBase + r;
            float4 v = make_float4(0.f, 0.f, 0.f, 0.f);
            if (gr < N_NODES) v = xin[gr * NC4 + ch * 4 + j];
            *(float4*)&xs[r * 20 + j * 4] = v;
        }
        __syncthreads();

        #pragma unroll
        for (int k4 = 0; k4 < CHUNK / 4; k4++) {
            float4 xv[4];
            #pragma unroll
            for (int i = 0; i < 4; i++)
                xv[i] = *(const float4*)&xs[(q + 32 * i) * 20 + k4 * 4];
            #pragma unroll
            for (int kk = 0; kk < 4; kk++) {
                int k = ch * CHUNK + k4 * 4 + kk;
                const double2* Wp = (const double2*)&Ws[k * 64 + cg * 8];
                double2 wA = Wp[0], wB = Wp[1];
                u64 w0 = __double_as_longlong(wA.x);
                u64 w1 = __double_as_longlong(wA.y);
                u64 w2 = __double_as_longlong(wB.x);
                u64 w3 = __double_as_longlong(wB.y);
                #pragma unroll
                for (int i = 0; i < 4; i++) {
                    float xf = (kk == 0) ? xv[i].x : (kk == 1) ? xv[i].y
                             : (kk == 2) ? xv[i].z : xv[i].w;
                    u64 xp;
                    asm("mov.b64 %0, {%1, %2};" : "=l"(xp) : "f"(xf), "f"(xf));
                    asm("fma.rn.f32x2 %0, %1, %2, %0;" : "+l"(acc[i][0]) : "l"(xp), "l"(w0));
                    asm("fma.rn.f32x2 %0, %1, %2, %0;" : "+l"(acc[i][1]) : "l"(xp), "l"(w1));
                    asm("fma.rn.f32x2 %0, %1, %2, %0;" : "+l"(acc[i][2]) : "l"(xp), "l"(w2));
                    asm("fma.rn.f32x2 %0, %1, %2, %0;" : "+l"(acc[i][3]) : "l"(xp), "l"(w3));
                }
            }
        }
    }

    #pragma unroll
    for (int i = 0; i < 4; i++) {
        int r = rowBase + q + 32 * i;
        if (r < N_NODES) {
            float4 o0, o1;
            asm("mov.b64 {%0, %1}, %2;" : "=f"(o0.x), "=f"(o0.y) : "l"(acc[i][0]));
            asm("mov.b64 {%0, %1}, %2;" : "=f"(o0.z), "=f"(o0.w) : "l"(acc[i][1]));
            asm("mov.b64 {%0, %1}, %2;" : "=f"(o1.x), "=f"(o1.y) : "l"(acc[i][2]));
            asm("mov.b64 {%0, %1}, %2;" : "=f"(o1.z), "=f"(o1.w) : "l"(acc[i][3]));
            ((float4*)g_h)[r * 16 + cg * 2]     = o0;
            ((float4*)g_h)[r * 16 + cg * 2 + 1] = o1;
        }
    }
}

// ---------------------------------------------------------------------------
// Gather 1: agg1[n] = relu( sum_{s in CSR[n]} h[s] ). 16 lanes/node, 4-way MLP.
// ---------------------------------------------------------------------------
__global__ void gather1_kernel() {
    const float4* h = (const float4*)g_h;
    float4* agg = (float4*)g_agg1;
    int t = blockIdx.x * blockDim.x + threadIdx.x;
    if (t >= N_NODES * 16) return;
    int n = t >> 4, c = t & 15;
    int b = g_off[n], e = g_off[n + 1];
    float4 acc = make_float4(0.f, 0.f, 0.f, 0.f);
    int i = b;
    for (; i + 3 < e; i += 4) {
        int s0 = g_csr[i], s1 = g_csr[i+1], s2 = g_csr[i+2], s3 = g_csr[i+3];
        float4 v0 = h[s0 * 16 + c];
        float4 v1 = h[s1 * 16 + c];
        float4 v2 = h[s2 * 16 + c];
        float4 v3 = h[s3 * 16 + c];
        acc.x += v0.x + v1.x + v2.x + v3.x;
        acc.y += v0.y + v1.y + v2.y + v3.y;
        acc.z += v0.z + v1.z + v2.z + v3.z;
        acc.w += v0.w + v1.w + v2.w + v3.w;
    }
    for (; i < e; i++) {
        int s = g_csr[i];
        float4 v = h[s * 16 + c];
        acc.x += v.x; acc.y += v.y; acc.z += v.z; acc.w += v.w;
    }
    acc.x = fmaxf(acc.x, 0.f); acc.y = fmaxf(acc.y, 0.f);
    acc.z = fmaxf(acc.z, 0.f); acc.w = fmaxf(acc.w, 0.f);
    agg[n * 16 + c] = acc;
}

// ---------------------------------------------------------------------------
// Gather 2 fused with pooling (flat form — independent threads, no barriers):
// pooled[batch[n]] += sum_{s in CSR[n]} agg1[s]
// ---------------------------------------------------------------------------
__global__ void gather2_pool_kernel(const int* __restrict__ batch) {
    const float4* h = (const float4*)g_agg1;
    int t = blockIdx.x * blockDim.x + threadIdx.x;
    if (t >= N_NODES * 16) return;
    int n = t >> 4, c = t & 15;
    int b = g_off[n], e = g_off[n + 1];
    float4 acc = make_float4(0.f, 0.f, 0.f, 0.f);
    int i = b;
    for (; i + 3 < e; i += 4) {
        int s0 = g_csr[i], s1 = g_csr[i+1], s2 = g_csr[i+2], s3 = g_csr[i+3];
        float4 v0 = h[s0 * 16 + c];
        float4 v1 = h[s1 * 16 + c];
        float4 v2 = h[s2 * 16 + c];
        float4 v3 = h[s3 * 16 + c];
        acc.x += v0.x + v1.x + v2.x + v3.x;
        acc.y += v0.y + v1.y + v2.y + v3.y;
        acc.z += v0.z + v1.z + v2.z + v3.z;
        acc.w += v0.w + v1.w + v2.w + v3.w;
    }
    for (; i < e; i++) {
        int s = g_csr[i];
        float4 v = h[s * 16 + c];
        acc.x += v.x; acc.y += v.y; acc.z += v.z; acc.w += v.w;
    }
    int g = batch[n];
    atomicAdd(&((float4*)g_pooled)[g * 16 + c], acc);
}

// ---------------------------------------------------------------------------
// Final: wv = W2 @ Wfc; counts via binary search on sorted batch;
// out[g] = sigmoid( dot(pooled[g], wv) / max(cnt,1) )
// ---------------------------------------------------------------------------
__global__ void final_kernel(const int* __restrict__ batch,
                             const float* __restrict__ W2,
                             const float* __restrict__ Wfc,
                             float* __restrict__ out) {
    __shared__ float wv[DIM];
    int tid = threadIdx.x;
    if (tid < DIM) {
        float s = 0.f;
        #pragma unroll
        for (int d = 0; d < DIM; d++)
            s += W2[tid * DIM + d] * Wfc[d];
        wv[tid] = s;
    }
    __syncthreads();
    if (tid >= N_GRAPHS) return;

    // count of nodes with batch == tid (batch sorted): lb(tid+1) - lb(tid)
    int lo = 0, hi = N_NODES;
    while (lo < hi) { int m = (lo + hi) >> 1; if (batch[m] < tid) lo = m + 1; else hi = m; }
    int b0 = lo;
    lo = 0; hi = N_NODES;
    while (lo < hi) { int m = (lo + hi) >> 1; if (batch[m] < tid + 1) lo = m + 1; else hi = m; }
    float cnt = fmaxf((float)(lo - b0), 1.0f);

    float s = 0.f;
    #pragma unroll
    for (int d = 0; d < DIM; d++)
        s += g_pooled[tid * DIM + d] * wv[d];
    s /= cnt;
    out[tid] = 1.0f / (1.0f + expf(-s));
}

// ---------------------------------------------------------------------------
extern "C" void kernel_launch(void* const* d_in, const int* in_sizes, int n_in,
                              void* d_out, int out_size) {
    const float* x    = (const float*)d_in[0];
    const int*   ei   = (const int*)d_in[1];
    const int*   batch= (const int*)d_in[2];
    const float* W1   = (const float*)d_in[3];
    const float* W2   = (const float*)d_in[4];
    const float* Wfc  = (const float*)d_in[5];
    float*       out  = (float*)d_out;

    zero_kernel<<<(N_NODES + 255) / 256, 256>>>();
    hist_kernel<<<(N_EDGES / 4 + 255) / 256, 256>>>(ei);
    scan_sums_kernel<<<SCAN_BLOCKS, 256>>>();
    scan_final_kernel<<<SCAN_BLOCKS, 256>>>();
    fill_kernel<<<(N_EDGES / 4 + 255) / 256, 256>>>(ei);

    gemm1_kernel<<<(N_NODES + 127) / 128, 256>>>((const float4*)x, W1);
    gather1_kernel<<<(N_NODES * 16) / 256, 256>>>();
    gather2_pool_kernel<<<(N_NODES * 16) / 256, 256>>>(batch);

    final_kernel<<<1, N_GRAPHS>>>(batch, W2, Wfc, out);
}

// round 9
// speedup vs baseline: 1.5526x; 1.0524x over previous
#include <cuda_runtime.h>
#include <cuda_bf16.h>

// Problem constants (match reference)
#define N_NODES 50000
#define N_EDGES 800000
#define N_FEAT  128
#define DIM     64
#define N_GRAPHS 512
#define SCAN_BLOCKS ((N_NODES + 255) / 256)   // 196

typedef unsigned long long u64;
typedef unsigned int u32;

// Scratch (device globals — no allocation allowed)
// Features stored as bf16 (halves gather traffic); accumulation stays fp32.
__device__ __align__(16) __nv_bfloat16 g_h[N_NODES * DIM];     // gemm1 out
__device__ __align__(16) __nv_bfloat16 g_agg1[N_NODES * DIM];  // relu(A@h1)
__device__ __align__(16) float g_pooled[N_GRAPHS * DIM];
// CSR (by destination)
__device__ __align__(16) int g_deg[N_NODES];
__device__ int g_off[N_NODES + 1];
__device__ int g_cursor[N_NODES];
__device__ int g_csr[N_EDGES];
__device__ int g_bsum[SCAN_BLOCKS];

// bf16x2 pack (round-to-nearest): hi=b, lo=a
__device__ __forceinline__ u32 pack_bf16x2(float a, float b) {
    u32 r;
    asm("cvt.rn.bf16x2.f32 %0, %1, %2;" : "=r"(r) : "f"(b), "f"(a));
    return r;
}
// exact bf16->fp32 unpack from packed u32
__device__ __forceinline__ float bf_lo(u32 u) { return __uint_as_float(u << 16); }
__device__ __forceinline__ float bf_hi(u32 u) { return __uint_as_float(u & 0xffff0000u); }

// ---------------------------------------------------------------------------
// Zero small state
// ---------------------------------------------------------------------------
__global__ void zero_kernel() {
    int i = blockIdx.x * blockDim.x + threadIdx.x;
    if (i < N_NODES) g_deg[i] = 0;
    if (i < N_GRAPHS * (DIM / 4))
        ((float4*)g_pooled)[i] = make_float4(0.f, 0.f, 0.f, 0.f);
    if (i == 0) g_off[N_NODES] = N_EDGES;   // known total
}

// ---------------------------------------------------------------------------
// CSR build: int4 histogram, 2-kernel scan, int4 atomic-bump fill
// ---------------------------------------------------------------------------
__global__ void hist_kernel(const int* __restrict__ ei) {
    int t = blockIdx.x * blockDim.x + threadIdx.x;
    if (t >= N_EDGES / 4) return;
    int4 d = ((const int4*)(ei + N_EDGES))[t];
    atomicAdd(&g_deg[d.x], 1);
    atomicAdd(&g_deg[d.y], 1);
    atomicAdd(&g_deg[d.z], 1);
    atomicAdd(&g_deg[d.w], 1);
}

__global__ void scan_sums_kernel() {
    __shared__ int sd[256];
    int tid = threadIdx.x;
    int i = blockIdx.x * 256 + tid;
    sd[tid] = (i < N_NODES) ? g_deg[i] : 0;
    __syncthreads();
    for (int s = 128; s > 0; s >>= 1) {
        if (tid < s) sd[tid] += sd[tid + s];
        __syncthreads();
    }
    if (tid == 0) g_bsum[blockIdx.x] = sd[0];
}

__global__ void scan_final_kernel() {
    __shared__ int red[256];
    __shared__ int wsum[8];
    __shared__ int blockBase;
    int tid = threadIdx.x;
    int bid = blockIdx.x;

    int part = 0;
    for (int t = tid; t < bid; t += 256) part += g_bsum[t];
    red[tid] = part;
    __syncthreads();
    for (int s = 128; s > 0; s >>= 1) {
        if (tid < s) red[tid] += red[tid + s];
        __syncthreads();
    }
    if (tid == 0) blockBase = red[0];

    int i = bid * 256 + tid;
    int v = (i < N_NODES) ? g_deg[i] : 0;
    int lane = tid & 31, wid = tid >> 5;
    int inc = v;
    #pragma unroll
    for (int off = 1; off < 32; off <<= 1) {
        int u = __shfl_up_sync(0xffffffff, inc, off);
        if (lane >= off) inc += u;
    }
    if (lane == 31) wsum[wid] = inc;
    __syncthreads();
    if (wid == 0) {
        int w = (lane < 8) ? wsum[lane] : 0;
        #pragma unroll
        for (int off = 1; off < 8; off <<= 1) {
            int u = __shfl_up_sync(0xffffffff, w, off);
            if (lane >= off) w += u;
        }
        if (lane < 8) wsum[lane] = w;
    }
    __syncthreads();
    int warpBase = (wid == 0) ? 0 : wsum[wid - 1];
    int excl = blockBase + warpBase + inc - v;
    if (i < N_NODES) {
        g_off[i] = excl;
        g_cursor[i] = excl;
    }
}

__global__ void fill_kernel(const int* __restrict__ ei) {
    int t = blockIdx.x * blockDim.x + threadIdx.x;
    if (t >= N_EDGES / 4) return;
    int4 s = ((const int4*)ei)[t];
    int4 d = ((const int4*)(ei + N_EDGES))[t];
    int p0 = atomicAdd(&g_cursor[d.x], 1);
    int p1 = atomicAdd(&g_cursor[d.y], 1);
    int p2 = atomicAdd(&g_cursor[d.z], 1);
    int p3 = atomicAdd(&g_cursor[d.w], 1);
    g_csr[p0] = s.x; g_csr[p1] = s.y; g_csr[p2] = s.z; g_csr[p3] = s.w;
}

// ---------------------------------------------------------------------------
// GEMM1: g_h[N,64](bf16) = x[N,128] @ W1[128,64], packed fma.rn.f32x2.
// Block = 256 threads / 128 rows; thread: 4 rows x 8 cols.
// ---------------------------------------------------------------------------
__global__ void gemm1_kernel(const float4* __restrict__ xin,
                             const float* __restrict__ W) {
    constexpr int K = N_FEAT;
    constexpr int NC4 = K / 4;
    constexpr int CHUNK = 16;
    constexpr int NCHUNK = K / CHUNK;
    __shared__ __align__(16) float Ws[K * 64];
    __shared__ __align__(16) float xs[128 * 20];

    int tid = threadIdx.x;
    for (int i = tid; i < K * 16; i += 256)
        ((float4*)Ws)[i] = ((const float4*)W)[i];

    int rowBase = blockIdx.x * 128;
    int q  = tid >> 3;
    int cg = tid & 7;

    u64 acc[4][4];
    #pragma unroll
    for (int i = 0; i < 4; i++)
        #pragma unroll
        for (int j = 0; j < 4; j++) acc[i][j] = 0ULL;

    for (int ch = 0; ch < NCHUNK; ch++) {
        __syncthreads();
        for (int l = tid; l < 512; l += 256) {
            int r = l >> 2, j = l & 3;
            int gr = rowBase + r;
            float4 v = make_float4(0.f, 0.f, 0.f, 0.f);
            if (gr < N_NODES) v = xin[gr * NC4 + ch * 4 + j];
            *(float4*)&xs[r * 20 + j * 4] = v;
        }
        __syncthreads();

        #pragma unroll
        for (int k4 = 0; k4 < CHUNK / 4; k4++) {
            float4 xv[4];
            #pragma unroll
            for (int i = 0; i < 4; i++)
                xv[i] = *(const float4*)&xs[(q + 32 * i) * 20 + k4 * 4];
            #pragma unroll
            for (int kk = 0; kk < 4; kk++) {
                int k = ch * CHUNK + k4 * 4 + kk;
                const double2* Wp = (const double2*)&Ws[k * 64 + cg * 8];
                double2 wA = Wp[0], wB = Wp[1];
                u64 w0 = __double_as_longlong(wA.x);
                u64 w1 = __double_as_longlong(wA.y);
                u64 w2 = __double_as_longlong(wB.x);
                u64 w3 = __double_as_longlong(wB.y);
                #pragma unroll
                for (int i = 0; i < 4; i++) {
                    float xf = (kk == 0) ? xv[i].x : (kk == 1) ? xv[i].y
                             : (kk == 2) ? xv[i].z : xv[i].w;
                    u64 xp;
                    asm("mov.b64 %0, {%1, %2};" : "=l"(xp) : "f"(xf), "f"(xf));
                    asm("fma.rn.f32x2 %0, %1, %2, %0;" : "+l"(acc[i][0]) : "l"(xp), "l"(w0));
                    asm("fma.rn.f32x2 %0, %1, %2, %0;" : "+l"(acc[i][1]) : "l"(xp), "l"(w1));
                    asm("fma.rn.f32x2 %0, %1, %2, %0;" : "+l"(acc[i][2]) : "l"(xp), "l"(w2));
                    asm("fma.rn.f32x2 %0, %1, %2, %0;" : "+l"(acc[i][3]) : "l"(xp), "l"(w3));
                }
            }
        }
    }

    // epilogue: pack 8 fp32 cols -> 4 bf16x2 -> one uint4 per row
    #pragma unroll
    for (int i = 0; i < 4; i++) {
        int r = rowBase + q + 32 * i;
        if (r < N_NODES) {
            float f[8];
            asm("mov.b64 {%0, %1}, %2;" : "=f"(f[0]), "=f"(f[1]) : "l"(acc[i][0]));
            asm("mov.b64 {%0, %1}, %2;" : "=f"(f[2]), "=f"(f[3]) : "l"(acc[i][1]));
            asm("mov.b64 {%0, %1}, %2;" : "=f"(f[4]), "=f"(f[5]) : "l"(acc[i][2]));
            asm("mov.b64 {%0, %1}, %2;" : "=f"(f[6]), "=f"(f[7]) : "l"(acc[i][3]));
            uint4 o;
            o.x = pack_bf16x2(f[0], f[1]);
            o.y = pack_bf16x2(f[2], f[3]);
            o.z = pack_bf16x2(f[4], f[5]);
            o.w = pack_bf16x2(f[6], f[7]);
            ((uint4*)g_h)[r * 8 + cg] = o;   // row = 64 bf16 = 8 uint4
        }
    }
}

// ---------------------------------------------------------------------------
// Gather 1: agg1[n] = relu( sum_{s in CSR[n]} h[s] ), bf16 in / fp32 acc / bf16 out.
// 8 lanes (uint4 of 8 bf16) per node, 4-way edge unroll.
// ---------------------------------------------------------------------------
__device__ __forceinline__ void acc_bf16x8(float* a, uint4 v) {
    a[0] += bf_lo(v.x); a[1] += bf_hi(v.x);
    a[2] += bf_lo(v.y); a[3] += bf_hi(v.y);
    a[4] += bf_lo(v.z); a[5] += bf_hi(v.z);
    a[6] += bf_lo(v.w); a[7] += bf_hi(v.w);
}

__global__ void gather1_kernel() {
    const uint4* h = (const uint4*)g_h;
    int t = blockIdx.x * blockDim.x + threadIdx.x;
    if (t >= N_NODES * 8) return;
    int n = t >> 3, c = t & 7;
    int b = g_off[n], e = g_off[n + 1];
    float a[8] = {0.f, 0.f, 0.f, 0.f, 0.f, 0.f, 0.f, 0.f};
    int i = b;
    for (; i + 3 < e; i += 4) {
        int s0 = g_csr[i], s1 = g_csr[i+1], s2 = g_csr[i+2], s3 = g_csr[i+3];
        uint4 v0 = h[s0 * 8 + c];
        uint4 v1 = h[s1 * 8 + c];
        uint4 v2 = h[s2 * 8 + c];
        uint4 v3 = h[s3 * 8 + c];
        acc_bf16x8(a, v0); acc_bf16x8(a, v1);
        acc_bf16x8(a, v2); acc_bf16x8(a, v3);
    }
    for (; i < e; i++) {
        uint4 v = h[g_csr[i] * 8 + c];
        acc_bf16x8(a, v);
    }
    #pragma unroll
    for (int j = 0; j < 8; j++) a[j] = fmaxf(a[j], 0.f);
    uint4 o;
    o.x = pack_bf16x2(a[0], a[1]);
    o.y = pack_bf16x2(a[2], a[3]);
    o.z = pack_bf16x2(a[4], a[5]);
    o.w = pack_bf16x2(a[6], a[7]);
    ((uint4*)g_agg1)[n * 8 + c] = o;
}

// ---------------------------------------------------------------------------
// Gather 2 fused with pooling: pooled[batch[n]] += sum_{s in CSR[n]} agg1[s]
// fp32 accumulation; two float4 REDs per lane.
// ---------------------------------------------------------------------------
__global__ void gather2_pool_kernel(const int* __restrict__ batch) {
    const uint4* h = (const uint4*)g_agg1;
    int t = blockIdx.x * blockDim.x + threadIdx.x;
    if (t >= N_NODES * 8) return;
    int n = t >> 3, c = t & 7;
    int b = g_off[n], e = g_off[n + 1];
    float a[8] = {0.f, 0.f, 0.f, 0.f, 0.f, 0.f, 0.f, 0.f};
    int i = b;
    for (; i + 3 < e; i += 4) {
        int s0 = g_csr[i], s1 = g_csr[i+1], s2 = g_csr[i+2], s3 = g_csr[i+3];
        uint4 v0 = h[s0 * 8 + c];
        uint4 v1 = h[s1 * 8 + c];
        uint4 v2 = h[s2 * 8 + c];
        uint4 v3 = h[s3 * 8 + c];
        acc_bf16x8(a, v0); acc_bf16x8(a, v1);
        acc_bf16x8(a, v2); acc_bf16x8(a, v3);
    }
    for (; i < e; i++) {
        uint4 v = h[g_csr[i] * 8 + c];
        acc_bf16x8(a, v);
    }
    int g = batch[n];
    float4* pooled = (float4*)g_pooled;   // row = 16 float4; lane c -> idx c*2, c*2+1
    atomicAdd(&pooled[g * 16 + c * 2],     make_float4(a[0], a[1], a[2], a[3]));
    atomicAdd(&pooled[g * 16 + c * 2 + 1], make_float4(a[4], a[5], a[6], a[7]));
}

// ---------------------------------------------------------------------------
// Final: wv = W2 @ Wfc; counts via binary search on sorted batch;
// out[g] = sigmoid( dot(pooled[g], wv) / max(cnt,1) )
// ---------------------------------------------------------------------------
__global__ void final_kernel(const int* __restrict__ batch,
                             const float* __restrict__ W2,
                             const float* __restrict__ Wfc,
                             float* __restrict__ out) {
    __shared__ float wv[DIM];
    int tid = threadIdx.x;
    if (tid < DIM) {
        float s = 0.f;
        #pragma unroll
        for (int d = 0; d < DIM; d++)
            s += W2[tid * DIM + d] * Wfc[d];
        wv[tid] = s;
    }
    __syncthreads();
    if (tid >= N_GRAPHS) return;

    int lo = 0, hi = N_NODES;
    while (lo < hi) { int m = (lo + hi) >> 1; if (batch[m] < tid) lo = m + 1; else hi = m; }
    int b0 = lo;
    lo = 0; hi = N_NODES;
    while (lo < hi) { int m = (lo + hi) >> 1; if (batch[m] < tid + 1) lo = m + 1; else hi = m; }
    float cnt = fmaxf((float)(lo - b0), 1.0f);

    float s = 0.f;
    #pragma unroll
    for (int d = 0; d < DIM; d++)
        s += g_pooled[tid * DIM + d] * wv[d];
    s /= cnt;
    out[tid] = 1.0f / (1.0f + expf(-s));
}

// ---------------------------------------------------------------------------
extern "C" void kernel_launch(void* const* d_in, const int* in_sizes, int n_in,
                              void* d_out, int out_size) {
    const float* x    = (const float*)d_in[0];
    const int*   ei   = (const int*)d_in[1];
    const int*   batch= (const int*)d_in[2];
    const float* W1   = (const float*)d_in[3];
    const float* W2   = (const float*)d_in[4];
    const float* Wfc  = (const float*)d_in[5];
    float*       out  = (float*)d_out;

    zero_kernel<<<(N_NODES + 255) / 256, 256>>>();
    hist_kernel<<<(N_EDGES / 4 + 255) / 256, 256>>>(ei);
    scan_sums_kernel<<<SCAN_BLOCKS, 256>>>();
    scan_final_kernel<<<SCAN_BLOCKS, 256>>>();
    fill_kernel<<<(N_EDGES / 4 + 255) / 256, 256>>>(ei);

    gemm1_kernel<<<(N_NODES + 127) / 128, 256>>>((const float4*)x, W1);
    gather1_kernel<<<(N_NODES * 8 + 255) / 256, 256>>>();
    gather2_pool_kernel<<<(N_NODES * 8 + 255) / 256, 256>>>(batch);

    final_kernel<<<1, N_GRAPHS>>>(batch, W2, Wfc, out);
}

// round 10
// speedup vs baseline: 1.8089x; 1.1651x over previous
#include <cuda_runtime.h>
#include <cuda_bf16.h>

// Problem constants (match reference)
#define N_NODES 50000
#define N_EDGES 800000
#define N_FEAT  128
#define DIM     64
#define N_GRAPHS 512
#define SCAN_BLOCKS ((N_NODES + 255) / 256)   // 196

typedef unsigned long long u64;
typedef unsigned int u32;

// Scratch (device globals — no allocation allowed)
// Features stored as bf16 (halves gather traffic); accumulation stays fp32.
__device__ __align__(16) __nv_bfloat16 g_h[N_NODES * DIM];     // gemm1 out
__device__ __align__(16) __nv_bfloat16 g_agg1[N_NODES * DIM];  // relu(A@h1)
__device__ __align__(16) float g_pooled[N_GRAPHS * DIM];
// CSR (by destination)
__device__ __align__(16) int g_deg[N_NODES];
__device__ int g_off[N_NODES + 1];
__device__ int g_cursor[N_NODES];
__device__ int g_csr[N_EDGES];
__device__ int g_bsum[SCAN_BLOCKS];

// bf16x2 pack (round-to-nearest): hi=b, lo=a
__device__ __forceinline__ u32 pack_bf16x2(float a, float b) {
    u32 r;
    asm("cvt.rn.bf16x2.f32 %0, %1, %2;" : "=r"(r) : "f"(b), "f"(a));
    return r;
}
// exact bf16->fp32 unpack from packed u32
__device__ __forceinline__ float bf_lo(u32 u) { return __uint_as_float(u << 16); }
__device__ __forceinline__ float bf_hi(u32 u) { return __uint_as_float(u & 0xffff0000u); }

// ---------------------------------------------------------------------------
// CSR build: int4 histogram, 2-kernel scan, int4 atomic-bump fill
// ---------------------------------------------------------------------------
__global__ void hist_kernel(const int* __restrict__ ei) {
    int t = blockIdx.x * blockDim.x + threadIdx.x;
    if (t >= N_EDGES / 4) return;
    int4 d = ((const int4*)(ei + N_EDGES))[t];
    atomicAdd(&g_deg[d.x], 1);
    atomicAdd(&g_deg[d.y], 1);
    atomicAdd(&g_deg[d.z], 1);
    atomicAdd(&g_deg[d.w], 1);
}

__global__ void scan_sums_kernel() {
    __shared__ int sd[256];
    int tid = threadIdx.x;
    int i = blockIdx.x * 256 + tid;
    sd[tid] = (i < N_NODES) ? g_deg[i] : 0;
    __syncthreads();
    for (int s = 128; s > 0; s >>= 1) {
        if (tid < s) sd[tid] += sd[tid + s];
        __syncthreads();
    }
    if (tid == 0) g_bsum[blockIdx.x] = sd[0];
}

__global__ void scan_final_kernel() {
    __shared__ int red[256];
    __shared__ int wsum[8];
    __shared__ int blockBase;
    int tid = threadIdx.x;
    int bid = blockIdx.x;

    int part = 0;
    for (int t = tid; t < bid; t += 256) part += g_bsum[t];
    red[tid] = part;
    __syncthreads();
    for (int s = 128; s > 0; s >>= 1) {
        if (tid < s) red[tid] += red[tid + s];
        __syncthreads();
    }
    if (tid == 0) blockBase = red[0];

    int i = bid * 256 + tid;
    int v = (i < N_NODES) ? g_deg[i] : 0;
    int lane = tid & 31, wid = tid >> 5;
    int inc = v;
    #pragma unroll
    for (int off = 1; off < 32; off <<= 1) {
        int u = __shfl_up_sync(0xffffffff, inc, off);
        if (lane >= off) inc += u;
    }
    if (lane == 31) wsum[wid] = inc;
    __syncthreads();
    if (wid == 0) {
        int w = (lane < 8) ? wsum[lane] : 0;
        #pragma unroll
        for (int off = 1; off < 8; off <<= 1) {
            int u = __shfl_up_sync(0xffffffff, w, off);
            if (lane >= off) w += u;
        }
        if (lane < 8) wsum[lane] = w;
    }
    __syncthreads();
    int warpBase = (wid == 0) ? 0 : wsum[wid - 1];
    int excl = blockBase + warpBase + inc - v;
    if (i < N_NODES) {
        g_off[i] = excl;
        g_cursor[i] = excl;
        if (i == N_NODES - 1) g_off[N_NODES] = excl + v;
    }
}

__global__ void fill_kernel(const int* __restrict__ ei) {
    int t = blockIdx.x * blockDim.x + threadIdx.x;
    if (t >= N_EDGES / 4) return;
    int4 s = ((const int4*)ei)[t];
    int4 d = ((const int4*)(ei + N_EDGES))[t];
    int p0 = atomicAdd(&g_cursor[d.x], 1);
    int p1 = atomicAdd(&g_cursor[d.y], 1);
    int p2 = atomicAdd(&g_cursor[d.z], 1);
    int p3 = atomicAdd(&g_cursor[d.w], 1);
    g_csr[p0] = s.x; g_csr[p1] = s.y; g_csr[p2] = s.z; g_csr[p3] = s.w;
}

// ---------------------------------------------------------------------------
// GEMM1: g_h[N,64](bf16) = x[N,128] @ W1[128,64], packed fma.rn.f32x2.
// Block = 256 threads / 128 rows; thread: 4 rows x 8 cols.
// ---------------------------------------------------------------------------
__global__ void gemm1_kernel(const float4* __restrict__ xin,
                             const float* __restrict__ W) {
    constexpr int K = N_FEAT;
    constexpr int NC4 = K / 4;
    constexpr int CHUNK = 16;
    constexpr int NCHUNK = K / CHUNK;
    __shared__ __align__(16) float Ws[K * 64];
    __shared__ __align__(16) float xs[128 * 20];

    int tid = threadIdx.x;
    for (int i = tid; i < K * 16; i += 256)
        ((float4*)Ws)[i] = ((const float4*)W)[i];

    int rowBase = blockIdx.x * 128;
    int q  = tid >> 3;
    int cg = tid & 7;

    u64 acc[4][4];
    #pragma unroll
    for (int i = 0; i < 4; i++)
        #pragma unroll
        for (int j = 0; j < 4; j++) acc[i][j] = 0ULL;

    for (int ch = 0; ch < NCHUNK; ch++) {
        __syncthreads();
        for (int l = tid; l < 512; l += 256) {
            int r = l >> 2, j = l & 3;
            int gr = rowBase + r;
            float4 v = make_float4(0.f, 0.f, 0.f, 0.f);
            if (gr < N_NODES) v = xin[gr * NC4 + ch * 4 + j];
            *(float4*)&xs[r * 20 + j * 4] = v;
        }
        __syncthreads();

        #pragma unroll
        for (int k4 = 0; k4 < CHUNK / 4; k4++) {
            float4 xv[4];
            #pragma unroll
            for (int i = 0; i < 4; i++)
                xv[i] = *(const float4*)&xs[(q + 32 * i) * 20 + k4 * 4];
            #pragma unroll
            for (int kk = 0; kk < 4; kk++) {
                int k = ch * CHUNK + k4 * 4 + kk;
                const double2* Wp = (const double2*)&Ws[k * 64 + cg * 8];
                double2 wA = Wp[0], wB = Wp[1];
                u64 w0 = __double_as_longlong(wA.x);
                u64 w1 = __double_as_longlong(wA.y);
                u64 w2 = __double_as_longlong(wB.x);
                u64 w3 = __double_as_longlong(wB.y);
                #pragma unroll
                for (int i = 0; i < 4; i++) {
                    float xf = (kk == 0) ? xv[i].x : (kk == 1) ? xv[i].y
                             : (kk == 2) ? xv[i].z : xv[i].w;
                    u64 xp;
                    asm("mov.b64 %0, {%1, %2};" : "=l"(xp) : "f"(xf), "f"(xf));
                    asm("fma.rn.f32x2 %0, %1, %2, %0;" : "+l"(acc[i][0]) : "l"(xp), "l"(w0));
                    asm("fma.rn.f32x2 %0, %1, %2, %0;" : "+l"(acc[i][1]) : "l"(xp), "l"(w1));
                    asm("fma.rn.f32x2 %0, %1, %2, %0;" : "+l"(acc[i][2]) : "l"(xp), "l"(w2));
                    asm("fma.rn.f32x2 %0, %1, %2, %0;" : "+l"(acc[i][3]) : "l"(xp), "l"(w3));
                }
            }
        }
    }

    // epilogue: pack 8 fp32 cols -> 4 bf16x2 -> one uint4 per row
    #pragma unroll
    for (int i = 0; i < 4; i++) {
        int r = rowBase + q + 32 * i;
        if (r < N_NODES) {
            float f[8];
            asm("mov.b64 {%0, %1}, %2;" : "=f"(f[0]), "=f"(f[1]) : "l"(acc[i][0]));
            asm("mov.b64 {%0, %1}, %2;" : "=f"(f[2]), "=f"(f[3]) : "l"(acc[i][1]));
            asm("mov.b64 {%0, %1}, %2;" : "=f"(f[4]), "=f"(f[5]) : "l"(acc[i][2]));
            asm("mov.b64 {%0, %1}, %2;" : "=f"(f[6]), "=f"(f[7]) : "l"(acc[i][3]));
            uint4 o;
            o.x = pack_bf16x2(f[0], f[1]);
            o.y = pack_bf16x2(f[2], f[3]);
            o.z = pack_bf16x2(f[4], f[5]);
            o.w = pack_bf16x2(f[6], f[7]);
            ((uint4*)g_h)[r * 8 + cg] = o;   // row = 64 bf16 = 8 uint4
        }
    }
}

// ---------------------------------------------------------------------------
// Gather 1: agg1[n] = relu( sum_{s in CSR[n]} h[s] ), bf16 in / fp32 acc / bf16 out.
// 8 lanes (uint4 of 8 bf16) per node, 4-way edge unroll.
// ---------------------------------------------------------------------------
__device__ __forceinline__ void acc_bf16x8(float* a, uint4 v) {
    a[0] += bf_lo(v.x); a[1] += bf_hi(v.x);
    a[2] += bf_lo(v.y); a[3] += bf_hi(v.y);
    a[4] += bf_lo(v.z); a[5] += bf_hi(v.z);
    a[6] += bf_lo(v.w); a[7] += bf_hi(v.w);
}

__global__ void gather1_kernel() {
    const uint4* h = (const uint4*)g_h;
    int t = blockIdx.x * blockDim.x + threadIdx.x;
    if (t >= N_NODES * 8) return;
    int n = t >> 3, c = t & 7;
    int b = g_off[n], e = g_off[n + 1];
    float a[8] = {0.f, 0.f, 0.f, 0.f, 0.f, 0.f, 0.f, 0.f};
    int i = b;
    for (; i + 3 < e; i += 4) {
        int s0 = g_csr[i], s1 = g_csr[i+1], s2 = g_csr[i+2], s3 = g_csr[i+3];
        uint4 v0 = h[s0 * 8 + c];
        uint4 v1 = h[s1 * 8 + c];
        uint4 v2 = h[s2 * 8 + c];
        uint4 v3 = h[s3 * 8 + c];
        acc_bf16x8(a, v0); acc_bf16x8(a, v1);
        acc_bf16x8(a, v2); acc_bf16x8(a, v3);
    }
    for (; i < e; i++) {
        uint4 v = h[g_csr[i] * 8 + c];
        acc_bf16x8(a, v);
    }
    #pragma unroll
    for (int j = 0; j < 8; j++) a[j] = fmaxf(a[j], 0.f);
    uint4 o;
    o.x = pack_bf16x2(a[0], a[1]);
    o.y = pack_bf16x2(a[2], a[3]);
    o.z = pack_bf16x2(a[4], a[5]);
    o.w = pack_bf16x2(a[6], a[7]);
    ((uint4*)g_agg1)[n * 8 + c] = o;
}

// ---------------------------------------------------------------------------
// Gather 2 fused with pooling: pooled[batch[n]] += sum_{s in CSR[n]} agg1[s]
// ---------------------------------------------------------------------------
__global__ void gather2_pool_kernel(const int* __restrict__ batch) {
    const uint4* h = (const uint4*)g_agg1;
    int t = blockIdx.x * blockDim.x + threadIdx.x;
    if (t >= N_NODES * 8) return;
    int n = t >> 3, c = t & 7;
    int b = g_off[n], e = g_off[n + 1];
    float a[8] = {0.f, 0.f, 0.f, 0.f, 0.f, 0.f, 0.f, 0.f};
    int i = b;
    for (; i + 3 < e; i += 4) {
        int s0 = g_csr[i], s1 = g_csr[i+1], s2 = g_csr[i+2], s3 = g_csr[i+3];
        uint4 v0 = h[s0 * 8 + c];
        uint4 v1 = h[s1 * 8 + c];
        uint4 v2 = h[s2 * 8 + c];
        uint4 v3 = h[s3 * 8 + c];
        acc_bf16x8(a, v0); acc_bf16x8(a, v1);
        acc_bf16x8(a, v2); acc_bf16x8(a, v3);
    }
    for (; i < e; i++) {
        uint4 v = h[g_csr[i] * 8 + c];
        acc_bf16x8(a, v);
    }
    int g = batch[n];
    float4* pooled = (float4*)g_pooled;   // row = 16 float4; lane c -> idx c*2, c*2+1
    atomicAdd(&pooled[g * 16 + c * 2],     make_float4(a[0], a[1], a[2], a[3]));
    atomicAdd(&pooled[g * 16 + c * 2 + 1], make_float4(a[4], a[5], a[6], a[7]));
}

// ---------------------------------------------------------------------------
// Final: wv = W2 @ Wfc; counts via binary search on sorted batch;
// out[g] = sigmoid( dot(pooled[g], wv) / max(cnt,1) )
// ---------------------------------------------------------------------------
__global__ void final_kernel(const int* __restrict__ batch,
                             const float* __restrict__ W2,
                             const float* __restrict__ Wfc,
                             float* __restrict__ out) {
    __shared__ float wv[DIM];
    int tid = threadIdx.x;
    if (tid < DIM) {
        float s = 0.f;
        #pragma unroll
        for (int d = 0; d < DIM; d++)
            s += W2[tid * DIM + d] * Wfc[d];
        wv[tid] = s;
    }
    __syncthreads();
    if (tid >= N_GRAPHS) return;

    int lo = 0, hi = N_NODES;
    while (lo < hi) { int m = (lo + hi) >> 1; if (batch[m] < tid) lo = m + 1; else hi = m; }
    int b0 = lo;
    lo = 0; hi = N_NODES;
    while (lo < hi) { int m = (lo + hi) >> 1; if (batch[m] < tid + 1) lo = m + 1; else hi = m; }
    float cnt = fmaxf((float)(lo - b0), 1.0f);

    float s = 0.f;
    #pragma unroll
    for (int d = 0; d < DIM; d++)
        s += g_pooled[tid * DIM + d] * wv[d];
    s /= cnt;
    out[tid] = 1.0f / (1.0f + expf(-s));
}

// ---------------------------------------------------------------------------
// One-time host resources (static init: NOT per-call state, no device alloc).
// Secondary stream + fork/join events for capture-legal parallelism; symbol
// addresses for memset nodes.
// ---------------------------------------------------------------------------
struct HostRes {
    cudaStream_t s2;
    cudaEvent_t evFork, evJoin;
    void* deg_ptr;
    void* pooled_ptr;
    HostRes() {
        cudaStreamCreateWithFlags(&s2, cudaStreamNonBlocking);
        cudaEventCreateWithFlags(&evFork, cudaEventDisableTiming);
        cudaEventCreateWithFlags(&evJoin, cudaEventDisableTiming);
        cudaGetSymbolAddress(&deg_ptr, g_deg);
        cudaGetSymbolAddress(&pooled_ptr, g_pooled);
    }
};
static HostRes g_hr;

// ---------------------------------------------------------------------------
extern "C" void kernel_launch(void* const* d_in, const int* in_sizes, int n_in,
                              void* d_out, int out_size) {
    const float* x    = (const float*)d_in[0];
    const int*   ei   = (const int*)d_in[1];
    const int*   batch= (const int*)d_in[2];
    const float* W1   = (const float*)d_in[3];
    const float* W2   = (const float*)d_in[4];
    const float* Wfc  = (const float*)d_in[5];
    float*       out  = (float*)d_out;

    // Fork: gemm1 runs on s2 concurrently with the CSR build on the main stream.
    cudaEventRecord(g_hr.evFork, 0);
    cudaStreamWaitEvent(g_hr.s2, g_hr.evFork, 0);
    gemm1_kernel<<<(N_NODES + 127) / 128, 256, 0, g_hr.s2>>>((const float4*)x, W1);

    // CSR build on main stream
    cudaMemsetAsync(g_hr.deg_ptr, 0, N_NODES * sizeof(int), 0);
    cudaMemsetAsync(g_hr.pooled_ptr, 0, N_GRAPHS * DIM * sizeof(float), 0);
    hist_kernel<<<(N_EDGES / 4 + 255) / 256, 256>>>(ei);
    scan_sums_kernel<<<SCAN_BLOCKS, 256>>>();
    scan_final_kernel<<<SCAN_BLOCKS, 256>>>();
    fill_kernel<<<(N_EDGES / 4 + 255) / 256, 256>>>(ei);

    // Join: gather1 needs both g_h (s2) and CSR (main).
    cudaEventRecord(g_hr.evJoin, g_hr.s2);
    cudaStreamWaitEvent(0, g_hr.evJoin, 0);

    gather1_kernel<<<(N_NODES * 8 + 255) / 256, 256>>>();
    gather2_pool_kernel<<<(N_NODES * 8 + 255) / 256, 256>>>(batch);
    final_kernel<<<1, N_GRAPHS>>>(batch, W2, Wfc, out);
}

// round 11
// speedup vs baseline: 1.8746x; 1.0363x over previous
#include <cuda_runtime.h>
#include <cuda_bf16.h>

// Problem constants (match reference)
#define N_NODES 50000
#define N_EDGES 800000
#define N_FEAT  128
#define DIM     64
#define N_GRAPHS 512
#define SCAN_BLOCKS ((N_NODES + 255) / 256)   // 196

typedef unsigned long long u64;
typedef unsigned int u32;

// Scratch (device globals — no allocation allowed)
__device__ __align__(16) __nv_bfloat16 g_h[N_NODES * DIM];     // gemm1 out
__device__ __align__(16) __nv_bfloat16 g_agg1[N_NODES * DIM];  // relu(A@h1)
__device__ __align__(16) float g_pooled[N_GRAPHS * DIM];
// CSR (by destination)
__device__ __align__(16) int g_deg[N_NODES];
__device__ int g_off[N_NODES + 1];
__device__ int g_cursor[N_NODES];
__device__ int g_csr[N_EDGES];

// bf16x2 pack (round-to-nearest): hi=b, lo=a
__device__ __forceinline__ u32 pack_bf16x2(float a, float b) {
    u32 r;
    asm("cvt.rn.bf16x2.f32 %0, %1, %2;" : "=r"(r) : "f"(b), "f"(a));
    return r;
}
__device__ __forceinline__ float bf_lo(u32 u) { return __uint_as_float(u << 16); }
__device__ __forceinline__ float bf_hi(u32 u) { return __uint_as_float(u & 0xffff0000u); }

// ---------------------------------------------------------------------------
// CSR build: int4 histogram, ONE-kernel scan, int4 atomic-bump fill
// ---------------------------------------------------------------------------
__global__ void hist_kernel(const int* __restrict__ ei) {
    int t = blockIdx.x * blockDim.x + threadIdx.x;
    if (t >= N_EDGES / 4) return;
    int4 d = ((const int4*)(ei + N_EDGES))[t];
    atomicAdd(&g_deg[d.x], 1);
    atomicAdd(&g_deg[d.y], 1);
    atomicAdd(&g_deg[d.z], 1);
    atomicAdd(&g_deg[d.w], 1);
}

// Each block: base = sum(deg[0..blockStart)) via coalesced strided reads
// (fully parallel across blocks), then shuffle exclusive scan of its 256 degs.
__global__ void scan_kernel() {
    __shared__ int red[256];
    __shared__ int wsum[8];
    __shared__ int blockBase;
    int tid = threadIdx.x;
    int bid = blockIdx.x;
    int start = bid * 256;

    int part = 0;
    for (int t = tid; t < start; t += 256) part += g_deg[t];
    red[tid] = part;
    __syncthreads();
    for (int s = 128; s > 0; s >>= 1) {
        if (tid < s) red[tid] += red[tid + s];
        __syncthreads();
    }
    if (tid == 0) blockBase = red[0];

    int i = start + tid;
    int v = (i < N_NODES) ? g_deg[i] : 0;
    int lane = tid & 31, wid = tid >> 5;
    int inc = v;
    #pragma unroll
    for (int off = 1; off < 32; off <<= 1) {
        int u = __shfl_up_sync(0xffffffff, inc, off);
        if (lane >= off) inc += u;
    }
    if (lane == 31) wsum[wid] = inc;
    __syncthreads();
    if (wid == 0) {
        int w = (lane < 8) ? wsum[lane] : 0;
        #pragma unroll
        for (int off = 1; off < 8; off <<= 1) {
            int u = __shfl_up_sync(0xffffffff, w, off);
            if (lane >= off) w += u;
        }
        if (lane < 8) wsum[lane] = w;
    }
    __syncthreads();
    int warpBase = (wid == 0) ? 0 : wsum[wid - 1];
    int excl = blockBase + warpBase + inc - v;
    if (i < N_NODES) {
        g_off[i] = excl;
        g_cursor[i] = excl;
        if (i == N_NODES - 1) g_off[N_NODES] = excl + v;
    }
}

__global__ void fill_kernel(const int* __restrict__ ei) {
    int t = blockIdx.x * blockDim.x + threadIdx.x;
    if (t >= N_EDGES / 4) return;
    int4 s = ((const int4*)ei)[t];
    int4 d = ((const int4*)(ei + N_EDGES))[t];
    int p0 = atomicAdd(&g_cursor[d.x], 1);
    int p1 = atomicAdd(&g_cursor[d.y], 1);
    int p2 = atomicAdd(&g_cursor[d.z], 1);
    int p3 = atomicAdd(&g_cursor[d.w], 1);
    g_csr[p0] = s.x; g_csr[p1] = s.y; g_csr[p2] = s.z; g_csr[p3] = s.w;
}

// ---------------------------------------------------------------------------
// GEMM1 v2: g_h[N,64](bf16) = x[N,128] @ W1[128,64], packed fma.rn.f32x2.
// Block = 256 threads, 256 rows. Thread: 8 rows (q+32i) x 8 cols.
// W LDS amortized over 8 rows -> FMA-bound inner loop.
// ---------------------------------------------------------------------------
__global__ void __launch_bounds__(256, 2) gemm1_kernel(
        const float4* __restrict__ xin, const float* __restrict__ W) {
    constexpr int K = N_FEAT;
    constexpr int NC4 = K / 4;
    constexpr int CHUNK = 16;
    constexpr int NCHUNK = K / CHUNK;
    constexpr int ROWS = 256;
    __shared__ __align__(16) float Ws[K * 64];        // 32 KB
    __shared__ __align__(16) float xs[ROWS * 20];     // 20 KB

    int tid = threadIdx.x;
    for (int i = tid; i < K * 16; i += 256)
        ((float4*)Ws)[i] = ((const float4*)W)[i];

    int rowBase = blockIdx.x * ROWS;
    int q  = tid >> 3;      // 0..31
    int cg = tid & 7;       // 0..7

    u64 acc[8][4];
    #pragma unroll
    for (int i = 0; i < 8; i++)
        #pragma unroll
        for (int j = 0; j < 4; j++) acc[i][j] = 0ULL;

    for (int ch = 0; ch < NCHUNK; ch++) {
        __syncthreads();   // covers Ws on first iteration
        // stage 256 rows x 16 k-floats = 1024 float4
        for (int l = tid; l < ROWS * 4; l += 256) {
            int r = l >> 2, j = l & 3;
            int gr = rowBase + r;
            float4 v = make_float4(0.f, 0.f, 0.f, 0.f);
            if (gr < N_NODES) v = xin[gr * NC4 + ch * 4 + j];
            *(float4*)&xs[r * 20 + j * 4] = v;
        }
        __syncthreads();

        #pragma unroll
        for (int k4 = 0; k4 < CHUNK / 4; k4++) {
            float4 xv[8];
            #pragma unroll
            for (int i = 0; i < 8; i++)
                xv[i] = *(const float4*)&xs[(q + 32 * i) * 20 + k4 * 4];
            #pragma unroll
            for (int kk = 0; kk < 4; kk++) {
                int k = ch * CHUNK + k4 * 4 + kk;
                const double2* Wp = (const double2*)&Ws[k * 64 + cg * 8];
                double2 wA = Wp[0], wB = Wp[1];
                u64 w0 = __double_as_longlong(wA.x);
                u64 w1 = __double_as_longlong(wA.y);
                u64 w2 = __double_as_longlong(wB.x);
                u64 w3 = __double_as_longlong(wB.y);
                #pragma unroll
                for (int i = 0; i < 8; i++) {
                    float xf = (kk == 0) ? xv[i].x : (kk == 1) ? xv[i].y
                             : (kk == 2) ? xv[i].z : xv[i].w;
                    u64 xp;
                    asm("mov.b64 %0, {%1, %2};" : "=l"(xp) : "f"(xf), "f"(xf));
                    asm("fma.rn.f32x2 %0, %1, %2, %0;" : "+l"(acc[i][0]) : "l"(xp), "l"(w0));
                    asm("fma.rn.f32x2 %0, %1, %2, %0;" : "+l"(acc[i][1]) : "l"(xp), "l"(w1));
                    asm("fma.rn.f32x2 %0, %1, %2, %0;" : "+l"(acc[i][2]) : "l"(xp), "l"(w2));
                    asm("fma.rn.f32x2 %0, %1, %2, %0;" : "+l"(acc[i][3]) : "l"(xp), "l"(w3));
                }
            }
        }
    }

    // epilogue: pack 8 fp32 cols -> 4 bf16x2 -> one uint4 per row
    #pragma unroll
    for (int i = 0; i < 8; i++) {
        int r = rowBase + q + 32 * i;
        if (r < N_NODES) {
            float f[8];
            asm("mov.b64 {%0, %1}, %2;" : "=f"(f[0]), "=f"(f[1]) : "l"(acc[i][0]));
            asm("mov.b64 {%0, %1}, %2;" : "=f"(f[2]), "=f"(f[3]) : "l"(acc[i][1]));
            asm("mov.b64 {%0, %1}, %2;" : "=f"(f[4]), "=f"(f[5]) : "l"(acc[i][2]));
            asm("mov.b64 {%0, %1}, %2;" : "=f"(f[6]), "=f"(f[7]) : "l"(acc[i][3]));
            uint4 o;
            o.x = pack_bf16x2(f[0], f[1]);
            o.y = pack_bf16x2(f[2], f[3]);
            o.z = pack_bf16x2(f[4], f[5]);
            o.w = pack_bf16x2(f[6], f[7]);
            ((uint4*)g_h)[r * 8 + cg] = o;
        }
    }
}

// ---------------------------------------------------------------------------
// Gathers: bf16 in / fp32 acc. 8 lanes (uint4 of 8 bf16) per node, 4-way unroll.
// ---------------------------------------------------------------------------
__device__ __forceinline__ void acc_bf16x8(float* a, uint4 v) {
    a[0] += bf_lo(v.x); a[1] += bf_hi(v.x);
    a[2] += bf_lo(v.y); a[3] += bf_hi(v.y);
    a[4] += bf_lo(v.z); a[5] += bf_hi(v.z);
    a[6] += bf_lo(v.w); a[7] += bf_hi(v.w);
}

__global__ void gather1_kernel() {
    const uint4* h = (const uint4*)g_h;
    int t = blockIdx.x * blockDim.x + threadIdx.x;
    if (t >= N_NODES * 8) return;
    int n = t >> 3, c = t & 7;
    int b = g_off[n], e = g_off[n + 1];
    float a[8] = {0.f, 0.f, 0.f, 0.f, 0.f, 0.f, 0.f, 0.f};
    int i = b;
    for (; i + 3 < e; i += 4) {
        int s0 = g_csr[i], s1 = g_csr[i+1], s2 = g_csr[i+2], s3 = g_csr[i+3];
        uint4 v0 = h[s0 * 8 + c];
        uint4 v1 = h[s1 * 8 + c];
        uint4 v2 = h[s2 * 8 + c];
        uint4 v3 = h[s3 * 8 + c];
        acc_bf16x8(a, v0); acc_bf16x8(a, v1);
        acc_bf16x8(a, v2); acc_bf16x8(a, v3);
    }
    for (; i < e; i++) {
        uint4 v = h[g_csr[i] * 8 + c];
        acc_bf16x8(a, v);
    }
    #pragma unroll
    for (int j = 0; j < 8; j++) a[j] = fmaxf(a[j], 0.f);
    uint4 o;
    o.x = pack_bf16x2(a[0], a[1]);
    o.y = pack_bf16x2(a[2], a[3]);
    o.z = pack_bf16x2(a[4], a[5]);
    o.w = pack_bf16x2(a[6], a[7]);
    ((uint4*)g_agg1)[n * 8 + c] = o;
}

__global__ void gather2_pool_kernel(const int* __restrict__ batch) {
    const uint4* h = (const uint4*)g_agg1;
    int t = blockIdx.x * blockDim.x + threadIdx.x;
    if (t >= N_NODES * 8) return;
    int n = t >> 3, c = t & 7;
    int b = g_off[n], e = g_off[n + 1];
    float a[8] = {0.f, 0.f, 0.f, 0.f, 0.f, 0.f, 0.f, 0.f};
    int i = b;
    for (; i + 3 < e; i += 4) {
        int s0 = g_csr[i], s1 = g_csr[i+1], s2 = g_csr[i+2], s3 = g_csr[i+3];
        uint4 v0 = h[s0 * 8 + c];
        uint4 v1 = h[s1 * 8 + c];
        uint4 v2 = h[s2 * 8 + c];
        uint4 v3 = h[s3 * 8 + c];
        acc_bf16x8(a, v0); acc_bf16x8(a, v1);
        acc_bf16x8(a, v2); acc_bf16x8(a, v3);
    }
    for (; i < e; i++) {
        uint4 v = h[g_csr[i] * 8 + c];
        acc_bf16x8(a, v);
    }
    int g = batch[n];
    float4* pooled = (float4*)g_pooled;
    atomicAdd(&pooled[g * 16 + c * 2],     make_float4(a[0], a[1], a[2], a[3]));
    atomicAdd(&pooled[g * 16 + c * 2 + 1], make_float4(a[4], a[5], a[6], a[7]));
}

// ---------------------------------------------------------------------------
// Final: wv = W2 @ Wfc; counts via binary search on sorted batch
// ---------------------------------------------------------------------------
__global__ void final_kernel(const int* __restrict__ batch,
                             const float* __restrict__ W2,
                             const float* __restrict__ Wfc,
                             float* __restrict__ out) {
    __shared__ float wv[DIM];
    int tid = threadIdx.x;
    if (tid < DIM) {
        float s = 0.f;
        #pragma unroll
        for (int d = 0; d < DIM; d++)
            s += W2[tid * DIM + d] * Wfc[d];
        wv[tid] = s;
    }
    __syncthreads();
    if (tid >= N_GRAPHS) return;

    int lo = 0, hi = N_NODES;
    while (lo < hi) { int m = (lo + hi) >> 1; if (batch[m] < tid) lo = m + 1; else hi = m; }
    int b0 = lo;
    lo = 0; hi = N_NODES;
    while (lo < hi) { int m = (lo + hi) >> 1; if (batch[m] < tid + 1) lo = m + 1; else hi = m; }
    float cnt = fmaxf((float)(lo - b0), 1.0f);

    float s = 0.f;
    #pragma unroll
    for (int d = 0; d < DIM; d++)
        s += g_pooled[tid * DIM + d] * wv[d];
    s /= cnt;
    out[tid] = 1.0f / (1.0f + expf(-s));
}

// ---------------------------------------------------------------------------
// One-time host resources (static init; no device alloc)
// ---------------------------------------------------------------------------
struct HostRes {
    cudaStream_t s2;
    cudaEvent_t evFork, evJoin;
    void* deg_ptr;
    void* pooled_ptr;
    HostRes() {
        cudaStreamCreateWithFlags(&s2, cudaStreamNonBlocking);
        cudaEventCreateWithFlags(&evFork, cudaEventDisableTiming);
        cudaEventCreateWithFlags(&evJoin, cudaEventDisableTiming);
        cudaGetSymbolAddress(&deg_ptr, g_deg);
        cudaGetSymbolAddress(&pooled_ptr, g_pooled);
    }
};
static HostRes g_hr;

// ---------------------------------------------------------------------------
extern "C" void kernel_launch(void* const* d_in, const int* in_sizes, int n_in,
                              void* d_out, int out_size) {
    const float* x    = (const float*)d_in[0];
    const int*   ei   = (const int*)d_in[1];
    const int*   batch= (const int*)d_in[2];
    const float* W1   = (const float*)d_in[3];
    const float* W2   = (const float*)d_in[4];
    const float* Wfc  = (const float*)d_in[5];
    float*       out  = (float*)d_out;

    // Fork: gemm1 (+ pooled memset) on s2, CSR build on main stream.
    cudaEventRecord(g_hr.evFork, 0);
    cudaStreamWaitEvent(g_hr.s2, g_hr.evFork, 0);
    cudaMemsetAsync(g_hr.pooled_ptr, 0, N_GRAPHS * DIM * sizeof(float), g_hr.s2);
    gemm1_kernel<<<(N_NODES + 255) / 256, 256, 0, g_hr.s2>>>((const float4*)x, W1);

    // CSR build on main stream
    cudaMemsetAsync(g_hr.deg_ptr, 0, N_NODES * sizeof(int), 0);
    hist_kernel<<<(N_EDGES / 4 + 255) / 256, 256>>>(ei);
    scan_kernel<<<SCAN_BLOCKS, 256>>>();
    fill_kernel<<<(N_EDGES / 4 + 255) / 256, 256>>>(ei);

    // Join: gather1 needs both g_h (s2) and CSR (main).
    cudaEventRecord(g_hr.evJoin, g_hr.s2);
    cudaStreamWaitEvent(0, g_hr.evJoin, 0);

    gather1_kernel<<<(N_NODES * 8 + 255) / 256, 256>>>();
    gather2_pool_kernel<<<(N_NODES * 8 + 255) / 256, 256>>>(batch);
    final_kernel<<<1, N_GRAPHS>>>(batch, W2, Wfc, out);
}